// round 16
// baseline (speedup 1.0000x reference)
#include <cuda_runtime.h>
#include <cuda_fp16.h>
#include <math.h>

typedef unsigned long long u64;

__device__ __forceinline__ u64 pk2(float x, float y) {
    u64 r; asm("mov.b64 %0,{%1,%2};" : "=l"(r) : "f"(x), "f"(y)); return r;
}
__device__ __forceinline__ float2 upk2(u64 v) {
    float2 r; asm("mov.b64 {%0,%1},%2;" : "=f"(r.x), "=f"(r.y) : "l"(v)); return r;
}
__device__ __forceinline__ u64 ffma2(u64 a, u64 b, u64 c) {
    u64 d; asm("fma.rn.f32x2 %0,%1,%2,%3;" : "=l"(d) : "l"(a), "l"(b), "l"(c)); return d;
}
__device__ __forceinline__ float2 h2f(unsigned u) {
    __half2 h = *reinterpret_cast<__half2*>(&u);
    return __half22float2(h);
}

// ---------------- scratch ----------------------------------------------------
__device__ float4 g_w4[128 * 128];
__device__ float  g_xf[64 * 128 * 256];
__device__ __half g_c1h[64 * 6 * 128 * 256];
__device__ __half g_pc1h[64 * 6 * 64 * 128];   // pooled raw c1
__device__ float  g_p1[64 * 6 * 64 * 128];
__device__ __half g_c2h[64 * 24 * 64 * 128];
__device__ __half g_pc2h[64 * 24 * 32 * 64];   // pooled raw c2
__device__ __half g_ah [64 * 24 * 32 * 64];
__device__ __half g_u3h[64 * 24 * 64 * 128];
__device__ __half g_u4h[64 * 12 * 128 * 256];

__device__ float g_part1[2048 * 12];
__device__ float g_part2[2048 * 12];
__device__ float g_part3[1024 * 24];
__device__ float g_part4[4096 * 12];
__device__ float g_part5[1024 * 12];

__device__ float2 g_sumc1[64 * 6];
__device__ float2 g_sumc2[64 * 24];

__device__ float g_tw4[64 * 2304];
__device__ float g_tb4[64 * 48];
__device__ float g_cf45a[64 * 114];
__device__ float g_cf45b[64 * 20];

// ---------------- reductions --------------------------------------------------
__device__ __forceinline__ float2 block_reduce2(float s, float s2) {
    __shared__ float sh[64];
    int lane = threadIdx.x & 31, wid = threadIdx.x >> 5;
#pragma unroll
    for (int o = 16; o; o >>= 1) {
        s  += __shfl_xor_sync(0xffffffffu, s, o);
        s2 += __shfl_xor_sync(0xffffffffu, s2, o);
    }
    if (lane == 0) { sh[wid] = s; sh[wid + 32] = s2; }
    __syncthreads();
    if (threadIdx.x == 0) {
        float a = 0.f, b = 0.f;
        int nw = (blockDim.x + 31) >> 5;
        for (int i = 0; i < nw; i++) { a += sh[i]; b += sh[i + 32]; }
        sh[0] = a; sh[32] = b;
    }
    __syncthreads();
    return make_float2(sh[0], sh[32]);
}

template <int M>
__device__ __forceinline__ float wgroup_reduce(float* v, int lane) {
#pragma unroll
    for (int half = M >> 1; half >= 1; half >>= 1) {
        bool up = (lane & half) != 0;
#pragma unroll
        for (int i = 0; i < half; i++) {
            float send = up ? v[i] : v[i + half];
            float keep = up ? v[i + half] : v[i];
            v[i] = keep + __shfl_xor_sync(0xffffffffu, send, half);
        }
    }
    float r = v[0];
#pragma unroll
    for (int o = M; o < 32; o <<= 1) r += __shfl_xor_sync(0xffffffffu, r, o);
    return r;
}

template <int N>  // N in {12,24}; blockDim == 256
__device__ __forceinline__ void block_preduce(float (&v)[N], float* gdst) {
    __shared__ float red[8][N];
    int lane = threadIdx.x & 31, wid = threadIdx.x >> 5;
    if (N == 24) {
        float a = wgroup_reduce<16>(v, lane);
        float b = wgroup_reduce<8>(v + 16, lane);
        if (lane < 16) red[wid][lane] = a;
        if (lane < 8)  red[wid][16 + lane] = b;
    } else {
        float a = wgroup_reduce<8>(v, lane);
        float b = wgroup_reduce<4>(v + 8, lane);
        if (lane < 8) red[wid][lane] = a;
        if (lane < 4) red[wid][8 + lane] = b;
    }
    __syncthreads();
    if (threadIdx.x < N) {
        float s = 0.f;
#pragma unroll
        for (int w = 0; w < 8; w++) s += red[w][threadIdx.x];
        gdst[threadIdx.x] = s;
    }
}

// ---------------- K0: pack fc1 weights ----------------------------------------
__global__ void k_prepw(const float* __restrict__ w) {
    int i = blockIdx.x * 256 + threadIdx.x;      // 16384
    int k = i >> 7, p = i & 127;
    int n0 = 2 * p;
    g_w4[i] = make_float4(w[n0 * 256 + k], w[(n0 + 1) * 256 + k],
                          w[n0 * 256 + k + 128], w[(n0 + 1) * 256 + k + 128]);
}

// ---------------- K1: Fourier + fc1 GEMM ---------------------------------------
__global__ void __launch_bounds__(256) k_fc1(const float* __restrict__ x,
                                             const float* __restrict__ Wf,
                                             const float* __restrict__ fb) {
    __shared__ float2 ssc[16][128];
    int m0 = blockIdx.x * 16;
    int t = threadIdx.x, tc = t & 31, tr = t >> 5;

    for (int e = t; e < 2048; e += 256) {
        int r = e >> 7, kk = e & 127;
        int m = m0 + r; int h = m & 127;
        float y = x[m * 128 + kk] * Wf[h * 128 + kk];
        float f = y - rintf(y);
        float ang = f * 6.283185307179586f;
        ssc[r][kk] = make_float2(__sinf(ang), __cosf(ang));
    }
    __syncthreads();

    u64 acc[2][4];
    u64 z = pk2(0.f, 0.f);
#pragma unroll
    for (int r = 0; r < 2; r++)
#pragma unroll
        for (int j = 0; j < 4; j++) acc[r][j] = z;

    const ulonglong2* Wp = (const ulonglong2*)g_w4;
#pragma unroll 4
    for (int k = 0; k < 128; k++) {
        ulonglong2 W[4];
#pragma unroll
        for (int j = 0; j < 4; j++) W[j] = __ldg(&Wp[k * 128 + tc + 32 * j]);
        float2 s0 = ssc[tr * 2][k];
        float2 s1 = ssc[tr * 2 + 1][k];
        u64 s0x = pk2(s0.x, s0.x), s0y = pk2(s0.y, s0.y);
        u64 s1x = pk2(s1.x, s1.x), s1y = pk2(s1.y, s1.y);
#pragma unroll
        for (int j = 0; j < 4; j++) {
            acc[0][j] = ffma2(s0x, W[j].x, acc[0][j]);
            acc[0][j] = ffma2(s0y, W[j].y, acc[0][j]);
            acc[1][j] = ffma2(s1x, W[j].x, acc[1][j]);
            acc[1][j] = ffma2(s1y, W[j].y, acc[1][j]);
        }
    }
    const float2* fb2 = (const float2*)fb;
#pragma unroll
    for (int r = 0; r < 2; r++) {
        int m = m0 + tr * 2 + r;
#pragma unroll
        for (int j = 0; j < 4; j++) {
            int p = tc + 32 * j;
            float2 a = upk2(acc[r][j]);
            float2 bi = __ldg(&fb2[p]);
            *(float2*)&g_xf[(size_t)m * 256 + 2 * p] = make_float2(a.x + bi.x, a.y + bi.y);
        }
    }
}

// ---------------- K2: conv1 3x3, 1->6, 2x2 px/thread + pooled output ------------
__global__ void __launch_bounds__(256) k_conv1(const float* __restrict__ ck,
                                               const float* __restrict__ cb) {
    __shared__ __align__(16) float sw[9][6];
    __shared__ float sb[6];
    int t = threadIdx.x;
    if (t < 54) { int oc = t / 9, tap = t % 9; sw[tap][oc] = ck[t]; }
    if (t < 6) sb[t] = cb[t];
    __syncthreads();

    int idx = blockIdx.x * 256 + t;              // 64 b * 64 hp * 128 wp
    int wp_ = idx & 127, hp = (idx >> 7) & 63, b = idx >> 13;
    int w0 = 2 * wp_, h0 = 2 * hp;
    const float* in = g_xf + (size_t)b * 32768;

    u64 vp[4][4];
#pragma unroll
    for (int i = 0; i < 4; i++) {
        int hy = h0 - 1 + i;
        bool rowok = (unsigned)hy < 128u;
        const float* base = in + hy * 256;
#pragma unroll
        for (int j = 0; j < 4; j++) {
            int wx = w0 - 1 + j;
            float v = (rowok && (unsigned)wx < 256u) ? base[wx] : 0.f;
            vp[i][j] = pk2(v, v);
        }
    }

    u64 z = pk2(0.f, 0.f);
    u64 acc[2][2][3];
#pragma unroll
    for (int r = 0; r < 2; r++)
#pragma unroll
        for (int c = 0; c < 2; c++)
#pragma unroll
            for (int j = 0; j < 3; j++) acc[r][c][j] = z;

#pragma unroll
    for (int ky = 0; ky < 3; ky++)
#pragma unroll
        for (int kx = 0; kx < 3; kx++) {
            const u64* wp = (const u64*)&sw[ky * 3 + kx][0];
            u64 w0v = wp[0], w1v = wp[1], w2v = wp[2];
#pragma unroll
            for (int r = 0; r < 2; r++)
#pragma unroll
                for (int c = 0; c < 2; c++) {
                    u64 vv = vp[r + ky][c + kx];
                    acc[r][c][0] = ffma2(vv, w0v, acc[r][c][0]);
                    acc[r][c][1] = ffma2(vv, w1v, acc[r][c][1]);
                    acc[r][c][2] = ffma2(vv, w2v, acc[r][c][2]);
                }
        }

    size_t ob = (size_t)b * 6 * 32768 + h0 * 256 + w0;   // halves
    float pv[12];
#pragma unroll
    for (int j = 0; j < 3; j++) {
        float b0 = sb[2 * j], b1 = sb[2 * j + 1];
        float2 a00 = upk2(acc[0][0][j]), a01 = upk2(acc[0][1][j]);
        float2 a10 = upk2(acc[1][0][j]), a11 = upk2(acc[1][1][j]);
        __half2 r0o0 = __floats2half2_rn(a00.x + b0, a01.x + b0);
        __half2 r0o1 = __floats2half2_rn(a00.y + b1, a01.y + b1);
        __half2 r1o0 = __floats2half2_rn(a10.x + b0, a11.x + b0);
        __half2 r1o1 = __floats2half2_rn(a10.y + b1, a11.y + b1);
        *(__half2*)(g_c1h + ob + (size_t)(2 * j) * 32768)           = r0o0;
        *(__half2*)(g_c1h + ob + (size_t)(2 * j) * 32768 + 256)     = r1o0;
        *(__half2*)(g_c1h + ob + (size_t)(2 * j + 1) * 32768)       = r0o1;
        *(__half2*)(g_c1h + ob + (size_t)(2 * j + 1) * 32768 + 256) = r1o1;
        float2 f00 = __half22float2(r0o0), f01 = __half22float2(r0o1);
        float2 f10 = __half22float2(r1o0), f11 = __half22float2(r1o1);
        float pm0 = fmaxf(fmaxf(f00.x, f00.y), fmaxf(f10.x, f10.y));
        float pm1 = fmaxf(fmaxf(f01.x, f01.y), fmaxf(f11.x, f11.y));
        size_t pb = (size_t)b * 6 * 8192 + hp * 128 + wp_;
        g_pc1h[pb + (size_t)(2 * j) * 8192]     = __float2half_rn(pm0);
        g_pc1h[pb + (size_t)(2 * j + 1) * 8192] = __float2half_rn(pm1);
        pv[2 * (2 * j)]         = (f00.x + f00.y) + (f10.x + f10.y);
        pv[2 * (2 * j) + 1]     = fmaf(f00.x, f00.x, f00.y * f00.y)
                                + fmaf(f10.x, f10.x, f10.y * f10.y);
        pv[2 * (2 * j + 1)]     = (f01.x + f01.y) + (f11.x + f11.y);
        pv[2 * (2 * j + 1) + 1] = fmaf(f01.x, f01.x, f01.y * f01.y)
                                + fmaf(f11.x, f11.x, f11.y * f11.y);
    }
    block_preduce<12>(pv, &g_part1[(size_t)blockIdx.x * 12]);
}

// ---------------- K3: GN1 apply + ReLU on pooled --------------------------------
__global__ void __launch_bounds__(256) k_gnpool1(const float* __restrict__ gamma,
                                                 const float* __restrict__ beta) {
    int bc = blockIdx.x >> 2, quarter = blockIdx.x & 3;
    int c = bc % 6, b = bc / 6;
    float s = 0.f, s2 = 0.f;
    if (threadIdx.x < 32) {
        const float* pp = &g_part1[(size_t)(b * 32 + threadIdx.x) * 12 + 2 * c];
        s = pp[0]; s2 = pp[1];
    }
    float2 r = block_reduce2(s, s2);
    if (quarter == 0 && threadIdx.x == 0) g_sumc1[bc] = make_float2(r.x, r.y);
    float mean = r.x * (1.f / 32768.f);
    float rstd = rsqrtf(r.y * (1.f / 32768.f) - mean * mean + 1e-5f);
    float A = rstd * gamma[c], Bv = beta[c] - mean * A;

    const __half* src = g_pc1h + (size_t)bc * 8192;
    float* q = g_p1 + (size_t)bc * 8192;
    int i = quarter * 2048 + threadIdx.x * 8;
    uint4 rv = *(const uint4*)(src + i);
    const unsigned* pr = &rv.x;
    float o[8];
#pragma unroll
    for (int j = 0; j < 4; j++) {
        float2 p = h2f(pr[j]);
        o[2 * j]     = fmaxf(fmaf(p.x, A, Bv), 0.f);
        o[2 * j + 1] = fmaxf(fmaf(p.y, A, Bv), 0.f);
    }
    *(float4*)(q + i)     = make_float4(o[0], o[1], o[2], o[3]);
    *(float4*)(q + i + 4) = make_float4(o[4], o[5], o[6], o[7]);
}

// ---------------- K4: conv2 3x3, 6->24, 2x2 px x 6oc/thread + pooled ------------
__global__ void __launch_bounds__(256) k_conv2(const float* __restrict__ ck,
                                               const float* __restrict__ cb) {
    __shared__ __align__(16) float sw[9 * 6 * 24];
    __shared__ float sb[24];
    int t = threadIdx.x;
    for (int i = t; i < 1296; i += 256) {
        int kx = i % 3, ky = (i / 3) % 3, ic = (i / 9) % 6, oc = i / 54;
        sw[((ky * 3 + kx) * 6 + ic) * 24 + oc] = ck[i];
    }
    if (t < 24) sb[t] = cb[t];
    __syncthreads();

    int blk = blockIdx.x;                        // 2048: b(64) x og2(4) x hb(8)
    int b = blk >> 5, og2 = (blk >> 3) & 3, hb = blk & 7;
    int wg = t & 63, hq = t >> 6;
    int hp = hb * 4 + hq;                        // pooled row 0..31
    int h0 = 2 * hp, w0 = 2 * wg;
    const float* in = g_p1 + (size_t)b * 6 * 8192;

    u64 z = pk2(0.f, 0.f);
    u64 acc[2][2][3];
#pragma unroll
    for (int r = 0; r < 2; r++)
#pragma unroll
        for (int c = 0; c < 2; c++)
#pragma unroll
            for (int j = 0; j < 3; j++) acc[r][c][j] = z;

#pragma unroll
    for (int ic = 0; ic < 6; ic++) {
        u64 vp[4][4];
#pragma unroll
        for (int i = 0; i < 4; i++) {
            int hy = h0 - 1 + i;
            bool rowok = (unsigned)hy < 64u;
            const float* rp = in + (size_t)ic * 8192 + hy * 128;
#pragma unroll
            for (int jx = 0; jx < 4; jx++) {
                int wx = w0 - 1 + jx;
                float v = (rowok && (unsigned)wx < 128u) ? rp[wx] : 0.f;
                vp[i][jx] = pk2(v, v);
            }
        }
#pragma unroll
        for (int ky = 0; ky < 3; ky++)
#pragma unroll
            for (int kx = 0; kx < 3; kx++) {
                const u64* wp = (const u64*)&sw[((ky * 3 + kx) * 6 + ic) * 24 + og2 * 6];
                u64 w0v = wp[0], w1v = wp[1], w2v = wp[2];
#pragma unroll
                for (int r = 0; r < 2; r++)
#pragma unroll
                    for (int c = 0; c < 2; c++) {
                        u64 vv = vp[r + ky][c + kx];
                        acc[r][c][0] = ffma2(vv, w0v, acc[r][c][0]);
                        acc[r][c][1] = ffma2(vv, w1v, acc[r][c][1]);
                        acc[r][c][2] = ffma2(vv, w2v, acc[r][c][2]);
                    }
            }
    }

    size_t ob = (size_t)b * 24 * 8192 + h0 * 128 + w0;   // halves
    size_t pb = (size_t)b * 24 * 2048 + hp * 64 + wg;    // pooled halves
    float pv[12];
#pragma unroll
    for (int j = 0; j < 3; j++) {
        int oc0 = og2 * 6 + 2 * j, oc1 = oc0 + 1;
        float b0 = sb[oc0], b1 = sb[oc1];
        float2 a00 = upk2(acc[0][0][j]), a01 = upk2(acc[0][1][j]);
        float2 a10 = upk2(acc[1][0][j]), a11 = upk2(acc[1][1][j]);
        __half2 r0o0 = __floats2half2_rn(a00.x + b0, a01.x + b0);
        __half2 r1o0 = __floats2half2_rn(a10.x + b0, a11.x + b0);
        __half2 r0o1 = __floats2half2_rn(a00.y + b1, a01.y + b1);
        __half2 r1o1 = __floats2half2_rn(a10.y + b1, a11.y + b1);
        *(__half2*)(g_c2h + ob + (size_t)oc0 * 8192)       = r0o0;
        *(__half2*)(g_c2h + ob + (size_t)oc0 * 8192 + 128) = r1o0;
        *(__half2*)(g_c2h + ob + (size_t)oc1 * 8192)       = r0o1;
        *(__half2*)(g_c2h + ob + (size_t)oc1 * 8192 + 128) = r1o1;
        float2 f00 = __half22float2(r0o0), f01 = __half22float2(r0o1);
        float2 f10 = __half22float2(r1o0), f11 = __half22float2(r1o1);
        float pm0 = fmaxf(fmaxf(f00.x, f00.y), fmaxf(f10.x, f10.y));
        float pm1 = fmaxf(fmaxf(f01.x, f01.y), fmaxf(f11.x, f11.y));
        g_pc2h[pb + (size_t)oc0 * 2048] = __float2half_rn(pm0);
        g_pc2h[pb + (size_t)oc1 * 2048] = __float2half_rn(pm1);
        pv[4 * j]     = (f00.x + f00.y) + (f10.x + f10.y);
        pv[4 * j + 1] = fmaf(f00.x, f00.x, f00.y * f00.y)
                      + fmaf(f10.x, f10.x, f10.y * f10.y);
        pv[4 * j + 2] = (f01.x + f01.y) + (f11.x + f11.y);
        pv[4 * j + 3] = fmaf(f01.x, f01.x, f01.y * f01.y)
                      + fmaf(f11.x, f11.x, f11.y * f11.y);
    }
    block_preduce<12>(pv, &g_part2[(size_t)blk * 12]);
}

// ---------------- K5: GN2 apply + ReLU + SiLU on pooled -------------------------
__global__ void __launch_bounds__(256) k_gnpool2(const float* __restrict__ gamma,
                                                 const float* __restrict__ beta) {
    int bc = blockIdx.x; int c = bc % 24, b = bc / 24;
    int og2 = c / 6, lc = c % 6;
    float s = 0.f, s2 = 0.f;
    if (threadIdx.x < 8) {
        const float* pp = &g_part2[(size_t)(b * 32 + og2 * 8 + threadIdx.x) * 12 + 2 * lc];
        s = pp[0]; s2 = pp[1];
    }
    float2 r = block_reduce2(s, s2);
    if (threadIdx.x == 0) g_sumc2[bc] = make_float2(r.x, r.y);
    float mean = r.x * (1.f / 8192.f);
    float rstd = rsqrtf(r.y * (1.f / 8192.f) - mean * mean + 1e-5f);
    float A = rstd * gamma[c], Bv = beta[c] - mean * A;

    const __half* src = g_pc2h + (size_t)bc * 2048;
    __half* q = g_ah + (size_t)bc * 2048;
    int i = threadIdx.x * 8;
    uint4 rv = *(const uint4*)(src + i);
    const unsigned* pr = &rv.x;
    float o[8];
#pragma unroll
    for (int j = 0; j < 4; j++) {
        float2 p = h2f(pr[j]);
        float v0 = fmaxf(fmaf(p.x, A, Bv), 0.f);
        float v1 = fmaxf(fmaf(p.y, A, Bv), 0.f);
        o[2 * j]     = v0 / (1.f + __expf(-v0));
        o[2 * j + 1] = v1 / (1.f + __expf(-v1));
    }
    __half2 h01 = __floats2half2_rn(o[0], o[1]);
    __half2 h23 = __floats2half2_rn(o[2], o[3]);
    __half2 h45 = __floats2half2_rn(o[4], o[5]);
    __half2 h67 = __floats2half2_rn(o[6], o[7]);
    uint4 st;
    st.x = *(unsigned*)&h01; st.y = *(unsigned*)&h23;
    st.z = *(unsigned*)&h45; st.w = *(unsigned*)&h67;
    *(uint4*)(q + i) = st;
}

// ---------------- K6: tconv3 2x2 s2, 24->24, 2px x 12oc per thread --------------
__global__ void __launch_bounds__(256) k_t3(const float* __restrict__ tk,
                                            const float* __restrict__ tb) {
    __shared__ __align__(16) float sw[2304];
    __shared__ float sb[24];
    int t = threadIdx.x;
    for (int i = t; i < 2304; i += 256) {
        int q = i & 1, d = (i >> 1) & 1, oc = (i >> 2) % 24, ic = i / 96;
        sw[((d * 24 + ic) * 24 + oc) * 2 + q] = tk[i];
    }
    if (t < 24) sb[t] = tb[t];
    __syncthreads();

    int blk = blockIdx.x;
    int b = blk >> 4, og = (blk >> 3) & 1, hb = blk & 7;
    int wg = t & 31, h = hb * 8 + (t >> 5);
    int wi0 = 2 * wg;
    int d = h & 1, hi = h >> 1;
    const ulonglong2* swu = (const ulonglong2*)sw;
    u64 z = pk2(0.f, 0.f);
    u64 acc0[12], acc1[12];
#pragma unroll
    for (int i = 0; i < 12; i++) { acc0[i] = z; acc1[i] = z; }

    const __half* base = g_ah + (size_t)b * 24 * 2048 + hi * 64 + wi0;
#pragma unroll 4
    for (int ic = 0; ic < 24; ic++) {
        unsigned vr = *(const unsigned*)(base + (size_t)ic * 2048);
        float2 v = h2f(vr);
        u64 va = pk2(v.x, v.x), vb = pk2(v.y, v.y);
        const ulonglong2* wp = swu + ((d * 24 + ic) * 24 + og * 12) / 2;
#pragma unroll
        for (int j = 0; j < 6; j++) {
            ulonglong2 w2 = wp[j];
            acc0[2 * j]     = ffma2(va, w2.x, acc0[2 * j]);
            acc1[2 * j]     = ffma2(vb, w2.x, acc1[2 * j]);
            acc0[2 * j + 1] = ffma2(va, w2.y, acc0[2 * j + 1]);
            acc1[2 * j + 1] = ffma2(vb, w2.y, acc1[2 * j + 1]);
        }
    }
    __half* ob = g_u3h + (size_t)b * 24 * 8192 + h * 128 + 4 * wg;
    float pv[24];
#pragma unroll
    for (int j = 0; j < 12; j++) {
        int oc = og * 12 + j;
        float bv = sb[oc];
        float2 a0 = upk2(acc0[j]);
        float2 a1 = upk2(acc1[j]);
        __half2 h01 = __floats2half2_rn(a0.x + bv, a0.y + bv);
        __half2 h23 = __floats2half2_rn(a1.x + bv, a1.y + bv);
        uint2 st; st.x = *(unsigned*)&h01; st.y = *(unsigned*)&h23;
        *(uint2*)(ob + (size_t)oc * 8192) = st;
        float2 r0 = __half22float2(h01), r1 = __half22float2(h23);
        pv[2 * j]     = (r0.x + r0.y) + (r1.x + r1.y);
        pv[2 * j + 1] = fmaf(r0.x, r0.x, r0.y * r0.y) + fmaf(r1.x, r1.x, r1.y * r1.y);
    }
    block_preduce<24>(pv, &g_part3[(size_t)blk * 24]);
}

// ---------------- K6b: t4 prep — gn3 stats + fold weights, per batch ------------
__global__ void __launch_bounds__(256) k_t4prep(const float* __restrict__ tk,
                                                const float* __restrict__ tb,
                                                const float* __restrict__ g3g,
                                                const float* __restrict__ g3b) {
    __shared__ float sA[48], sB[48];
    __shared__ float sc3[48][2];
    __shared__ float sm3[6], sr3[6];
    int t = threadIdx.x;
    int b = blockIdx.x;

    if (t < 48) {
        float s = 0.f, s2 = 0.f;
        if (t < 24) {
            float2 v = g_sumc2[b * 24 + t];
            s = v.x; s2 = v.y;
        } else {
            int j = t - 24, ogc = j / 12, lj = j % 12;
            const float* p = &g_part3[(size_t)(b * 16 + ogc * 8) * 24 + 2 * lj];
#pragma unroll
            for (int k = 0; k < 8; k++) { s += p[k * 24]; s2 += p[k * 24 + 1]; }
        }
        sc3[t][0] = s; sc3[t][1] = s2;
    }
    __syncthreads();
    if (t < 6) {
        float s = 0.f, s2 = 0.f;
        for (int j = 0; j < 8; j++) { s += sc3[t * 8 + j][0]; s2 += sc3[t * 8 + j][1]; }
        float mean = s * (1.f / 65536.f);
        sm3[t] = mean;
        sr3[t] = rsqrtf(s2 * (1.f / 65536.f) - mean * mean + 1e-5f);
    }
    __syncthreads();
    if (t < 48) {
        int g = t >> 3;
        float A = sr3[g] * g3g[t];
        sA[t] = A;
        sB[t] = g3b[t] - sm3[g] * A;
    }
    __syncthreads();
    float* tw = g_tw4 + (size_t)b * 2304;
    for (int i = t; i < 2304; i += 256) {
        int q = i & 1, d = (i >> 1) & 1, oc = (i >> 2) % 12, ic = i / 48;
        tw[((d * 48 + ic) * 12 + oc) * 2 + q] = sA[ic] * tk[i];
    }
    if (t < 48) {
        int q = t & 1, d = (t >> 1) & 1, oc = t >> 2;
        float bsum = tb[oc];
        for (int ic = 0; ic < 48; ic++)
            bsum = fmaf(sB[ic], tk[((ic * 12 + oc) * 2 + d) * 2 + q], bsum);
        g_tb4[b * 48 + d * 24 + oc * 2 + q] = bsum;
    }
}

// ---------------- K7: tconv4 48->12, prefolded weights, 2px x 6oc ---------------
__global__ void __launch_bounds__(256) k_t4() {
    __shared__ __align__(16) float sw[2304];
    __shared__ float sbias[2][12][2];
    int t = threadIdx.x;
    int blk = blockIdx.x;
    int b = blk >> 6, og = (blk >> 5) & 1, hb = blk & 31;

    const float4* wsrc = (const float4*)(g_tw4 + (size_t)b * 2304);
    float4* swv = (float4*)sw;
    for (int i = t; i < 576; i += 256) swv[i] = wsrc[i];
    if (t < 48) ((float*)sbias)[t] = g_tb4[b * 48 + t];
    __syncthreads();

    int wg = t & 63, h = hb * 4 + (t >> 6);
    int wi0 = 2 * wg;
    int d = h & 1, hi = h >> 1;
    const ulonglong2* swu = (const ulonglong2*)sw;
    u64 z = pk2(0.f, 0.f);
    u64 acc0[6], acc1[6];
#pragma unroll
    for (int i = 0; i < 6; i++) { acc0[i] = z; acc1[i] = z; }

    const __half* c2b = g_c2h + (size_t)b * 24 * 8192 + hi * 128 + wi0;
    const __half* u3b = g_u3h + (size_t)b * 24 * 8192 + hi * 128 + wi0;
#pragma unroll 4
    for (int ic = 0; ic < 24; ic++) {
        unsigned vr = *(const unsigned*)(c2b + (size_t)ic * 8192);
        float2 v = h2f(vr);
        u64 va = pk2(v.x, v.x), vb = pk2(v.y, v.y);
        const ulonglong2* wp = swu + ((d * 48 + ic) * 12 + og * 6) / 2;
        ulonglong2 wA = wp[0], wB = wp[1], wC = wp[2];
        acc0[0] = ffma2(va, wA.x, acc0[0]); acc1[0] = ffma2(vb, wA.x, acc1[0]);
        acc0[1] = ffma2(va, wA.y, acc0[1]); acc1[1] = ffma2(vb, wA.y, acc1[1]);
        acc0[2] = ffma2(va, wB.x, acc0[2]); acc1[2] = ffma2(vb, wB.x, acc1[2]);
        acc0[3] = ffma2(va, wB.y, acc0[3]); acc1[3] = ffma2(vb, wB.y, acc1[3]);
        acc0[4] = ffma2(va, wC.x, acc0[4]); acc1[4] = ffma2(vb, wC.x, acc1[4]);
        acc0[5] = ffma2(va, wC.y, acc0[5]); acc1[5] = ffma2(vb, wC.y, acc1[5]);
    }
#pragma unroll 4
    for (int ic = 0; ic < 24; ic++) {
        unsigned vr = *(const unsigned*)(u3b + (size_t)ic * 8192);
        float2 v = h2f(vr);
        u64 va = pk2(v.x, v.x), vb = pk2(v.y, v.y);
        const ulonglong2* wp = swu + ((d * 48 + 24 + ic) * 12 + og * 6) / 2;
        ulonglong2 wA = wp[0], wB = wp[1], wC = wp[2];
        acc0[0] = ffma2(va, wA.x, acc0[0]); acc1[0] = ffma2(vb, wA.x, acc1[0]);
        acc0[1] = ffma2(va, wA.y, acc0[1]); acc1[1] = ffma2(vb, wA.y, acc1[1]);
        acc0[2] = ffma2(va, wB.x, acc0[2]); acc1[2] = ffma2(vb, wB.x, acc1[2]);
        acc0[3] = ffma2(va, wB.y, acc0[3]); acc1[3] = ffma2(vb, wB.y, acc1[3]);
        acc0[4] = ffma2(va, wC.x, acc0[4]); acc1[4] = ffma2(vb, wC.x, acc1[4]);
        acc0[5] = ffma2(va, wC.y, acc0[5]); acc1[5] = ffma2(vb, wC.y, acc1[5]);
    }
    __half* ob = g_u4h + (size_t)b * 12 * 32768 + (size_t)h * 256 + 4 * wg;
    float pv[12];
#pragma unroll
    for (int j = 0; j < 6; j++) {
        int oc = og * 6 + j;
        float b0 = sbias[d][oc][0], b1 = sbias[d][oc][1];
        float2 a0 = upk2(acc0[j]);
        float2 a1 = upk2(acc1[j]);
        __half2 ha = __floats2half2_rn(a0.x + b0, a0.y + b1);
        __half2 hb2 = __floats2half2_rn(a1.x + b0, a1.y + b1);
        uint2 st; st.x = *(unsigned*)&ha; st.y = *(unsigned*)&hb2;
        *(uint2*)(ob + (size_t)oc * 32768) = st;
        float2 r0 = __half22float2(ha), r1 = __half22float2(hb2);
        pv[2 * j]     = (r0.x + r0.y) + (r1.x + r1.y);
        pv[2 * j + 1] = fmaf(r0.x, r0.x, r0.y * r0.y) + fmaf(r1.x, r1.x, r1.y * r1.y);
    }
    block_preduce<12>(pv, &g_part4[(size_t)blk * 12]);
}

// ---------------- K7b: p45a — gn4 stats + gn4t5 coefs, per batch ----------------
__global__ void __launch_bounds__(128) k_p45a(const float* __restrict__ g4g,
                                              const float* __restrict__ g4b,
                                              const float* __restrict__ t5k,
                                              const float* __restrict__ t5b) {
    __shared__ float sc4[18][2];
    __shared__ float sm4[6], sr4[6];
    int t = threadIdx.x;
    int b = blockIdx.x;

    if (t < 18) {
        float s = 0.f, s2 = 0.f;
        if (t < 6) {
            float2 v = g_sumc1[b * 6 + t];
            s = v.x; s2 = v.y;
        } else {
            int j = t - 6, ogc = j / 6, lj = j % 6;
            const float* p = &g_part4[(size_t)(b * 64 + ogc * 32) * 12 + 2 * lj];
#pragma unroll 8
            for (int k = 0; k < 32; k++) { s += p[k * 12]; s2 += p[k * 12 + 1]; }
        }
        sc4[t][0] = s; sc4[t][1] = s2;
    }
    __syncthreads();
    if (t < 6) {
        float s = 0.f, s2 = 0.f;
        for (int j = 0; j < 3; j++) { s += sc4[t * 3 + j][0]; s2 += sc4[t * 3 + j][1]; }
        float mean = s * (1.f / 98304.f);
        sm4[t] = mean;
        sr4[t] = rsqrtf(s2 * (1.f / 98304.f) - mean * mean + 1e-5f);
    }
    __syncthreads();
    if (t < 108) {
        int c = t / 6, o = t % 6;
        float A = sr4[c / 3] * g4g[c];
        g_cf45a[b * 114 + t] = A * t5k[o * 18 + c];
    }
    if (t >= 108 && t < 114) {
        int o = t - 108;
        float cc = t5b[o];
        for (int c = 0; c < 18; c++) {
            float A  = sr4[c / 3] * g4g[c];
            float Bv = g4b[c] - sm4[c / 3] * A;
            cc = fmaf(Bv, t5k[o * 18 + c], cc);
        }
        g_cf45a[b * 114 + 108 + o] = cc;
    }
}

// ---------------- K8: GN4+t5 stats-only, 8px/thread -----------------------------
__global__ void __launch_bounds__(256) k_gn4t5s() {
    __shared__ u64 W2d[18][6];
    __shared__ float cstp[6];
    int t = threadIdx.x;
    int b = blockIdx.x >> 4;
    int sp0 = ((blockIdx.x & 15) * 256 + t) * 8;

    if (t < 108) {
        float w = g_cf45a[b * 114 + t];
        ((u64*)W2d)[t] = pk2(w, w);
    }
    if (t >= 108 && t < 114) cstp[t - 108] = g_cf45a[b * 114 + t];
    __syncthreads();

    u64 acc[6][4];
#pragma unroll
    for (int o = 0; o < 6; o++) {
        u64 ic = pk2(cstp[o], cstp[o]);
#pragma unroll
        for (int k = 0; k < 4; k++) acc[o][k] = ic;
    }
    const __half* c1b = g_c1h + (size_t)b * 6 * 32768;
    const __half* u4b = g_u4h + (size_t)b * 12 * 32768;
#pragma unroll 2
    for (int c = 0; c < 18; c++) {
        const __half* src = (c < 6) ? (c1b + (size_t)c * 32768)
                                    : (u4b + (size_t)(c - 6) * 32768);
        uint4 rv = *(const uint4*)(src + sp0);
        const unsigned* pr = &rv.x;
        u64 vp[4];
#pragma unroll
        for (int k = 0; k < 4; k++) {
            float2 f = h2f(pr[k]);
            vp[k] = pk2(f.x, f.y);
        }
#pragma unroll
        for (int o = 0; o < 6; o++) {
            u64 w = W2d[c][o];
#pragma unroll
            for (int k = 0; k < 4; k++) acc[o][k] = ffma2(vp[k], w, acc[o][k]);
        }
    }
    float pv[12];
#pragma unroll
    for (int o = 0; o < 6; o++) {
        float s = 0.f, s2 = 0.f;
#pragma unroll
        for (int k = 0; k < 4; k++) {
            float2 a = upk2(acc[o][k]);
            s += a.x + a.y;
            s2 += fmaf(a.x, a.x, a.y * a.y);
        }
        pv[2 * o] = s; pv[2 * o + 1] = s2;
    }
    block_preduce<12>(pv, &g_part5[(size_t)blockIdx.x * 12]);
}

// ---------------- K8b: p45b — gn5 stats + final coefs, per batch ----------------
__global__ void __launch_bounds__(32) k_p45b(const float* __restrict__ tt,
                                             const float* __restrict__ g5g,
                                             const float* __restrict__ g5b,
                                             const float* __restrict__ fk,
                                             const float* __restrict__ fb2) {
    __shared__ float sm5[6], sr5[6];
    int t = threadIdx.x;
    int b = blockIdx.x;

    if (t < 6) {
        float s = 0.f, s2 = 0.f;
        const float* p = &g_part5[(size_t)(b * 16) * 12 + 2 * t];
#pragma unroll
        for (int k = 0; k < 16; k++) { s += p[k * 12]; s2 += p[k * 12 + 1]; }
        float mean = s * (1.f / 32768.f);
        sm5[t] = mean;
        sr5[t] = rsqrtf(s2 * (1.f / 32768.f) - mean * mean + 1e-5f);
    }
    __syncwarp();
    if (t < 18) {
        float s = 0.f;
        for (int c = 0; c < 6; c++) {
            float A5 = sr5[c] * g5g[c];
            s = fmaf(A5 * fk[c], g_cf45a[b * 114 + t * 6 + c], s);
        }
        g_cf45b[b * 20 + t] = s;
    }
    if (t == 18) {
        float cc = fb2[0];
        for (int c = 0; c < 6; c++) {
            float A5 = sr5[c] * g5g[c];
            float B5 = g5b[c] - sm5[c] * A5;
            cc += fk[c] * fmaf(A5, g_cf45a[b * 114 + 108 + c], B5);
        }
        g_cf45b[b * 20 + 18] = cc;
    }
    if (t == 19) {
        float tv = tt[b];
        float s2v = (expf(tv * 6.437751649736401f) - 1.f) * (1.f / 6.437751649736401f);
        g_cf45b[b * 20 + 19] = rsqrtf(s2v);
    }
}

// ---------------- K9: final 18->1 + /std, 8px/thread ----------------------------
__global__ void __launch_bounds__(256) k_final(float* __restrict__ out) {
    __shared__ u64 coefd[18];
    __shared__ float constb, istd;
    int t = threadIdx.x;
    int b = blockIdx.x >> 4;
    int sp0 = ((blockIdx.x & 15) * 256 + t) * 8;

    if (t < 18) {
        float s = g_cf45b[b * 20 + t];
        coefd[t] = pk2(s, s);
    }
    if (t == 18) constb = g_cf45b[b * 20 + 18];
    if (t == 19) istd = g_cf45b[b * 20 + 19];
    __syncthreads();

    u64 acc[4];
    u64 ci = pk2(constb, constb);
#pragma unroll
    for (int k = 0; k < 4; k++) acc[k] = ci;
    const __half* c1b = g_c1h + (size_t)b * 6 * 32768;
    const __half* u4b = g_u4h + (size_t)b * 12 * 32768;
#pragma unroll 2
    for (int c = 0; c < 18; c++) {
        const __half* src = (c < 6) ? (c1b + (size_t)c * 32768)
                                    : (u4b + (size_t)(c - 6) * 32768);
        uint4 rv = *(const uint4*)(src + sp0);
        const unsigned* pr = &rv.x;
        u64 w = coefd[c];
#pragma unroll
        for (int k = 0; k < 4; k++) {
            float2 f = h2f(pr[k]);
            acc[k] = ffma2(pk2(f.x, f.y), w, acc[k]);
        }
    }
    float sc = istd;
    float2 a0 = upk2(acc[0]), a1 = upk2(acc[1]), a2 = upk2(acc[2]), a3 = upk2(acc[3]);
    float* op = out + (size_t)b * 32768 + sp0;
    *(float4*)op = make_float4(a0.x * sc, a0.y * sc, a1.x * sc, a1.y * sc);
    *(float4*)(op + 4) = make_float4(a2.x * sc, a2.y * sc, a3.x * sc, a3.y * sc);
}

// ---------------- launcher -------------------------------------------------------
extern "C" void kernel_launch(void* const* d_in, const int* in_sizes, int n_in,
                              void* d_out, int out_size) {
    const float* x       = (const float*)d_in[0];
    const float* t       = (const float*)d_in[1];
    const float* Wf      = (const float*)d_in[2];
    const float* fc1_w   = (const float*)d_in[3];
    const float* fc1_b   = (const float*)d_in[4];
    const float* conv1_k = (const float*)d_in[5];
    const float* conv1_b = (const float*)d_in[6];
    const float* gn1_g   = (const float*)d_in[7];
    const float* gn1_b   = (const float*)d_in[8];
    const float* conv2_k = (const float*)d_in[9];
    const float* conv2_b = (const float*)d_in[10];
    const float* gn2_g   = (const float*)d_in[11];
    const float* gn2_b   = (const float*)d_in[12];
    const float* t3_k    = (const float*)d_in[13];
    const float* t3_b    = (const float*)d_in[14];
    const float* gn3_g   = (const float*)d_in[15];
    const float* gn3_b   = (const float*)d_in[16];
    const float* t4_k    = (const float*)d_in[17];
    const float* t4_b    = (const float*)d_in[18];
    const float* gn4_g   = (const float*)d_in[19];
    const float* gn4_b   = (const float*)d_in[20];
    const float* t5_k    = (const float*)d_in[21];
    const float* t5_b    = (const float*)d_in[22];
    const float* gn5_g   = (const float*)d_in[23];
    const float* gn5_b   = (const float*)d_in[24];
    const float* fin_k   = (const float*)d_in[25];
    const float* fin_b   = (const float*)d_in[26];
    float* out = (float*)d_out;

    k_prepw<<<64, 256>>>(fc1_w);
    k_fc1<<<512, 256>>>(x, Wf, fc1_b);
    k_conv1<<<2048, 256>>>(conv1_k, conv1_b);
    k_gnpool1<<<1536, 256>>>(gn1_g, gn1_b);
    k_conv2<<<2048, 256>>>(conv2_k, conv2_b);
    k_gnpool2<<<1536, 256>>>(gn2_g, gn2_b);
    k_t3<<<1024, 256>>>(t3_k, t3_b);
    k_t4prep<<<64, 256>>>(t4_k, t4_b, gn3_g, gn3_b);
    k_t4<<<4096, 256>>>();
    k_p45a<<<64, 128>>>(gn4_g, gn4_b, t5_k, t5_b);
    k_gn4t5s<<<1024, 256>>>();
    k_p45b<<<64, 32>>>(t, gn5_g, gn5_b, fin_k, fin_b);
    k_final<<<1024, 256>>>(out);
}